// round 9
// baseline (speedup 1.0000x reference)
#include <cuda_runtime.h>

// BoxLoss: 3-scale YOLO box loss. ONE launch, 32 blocks (1 image each),
// 192 threads = 3 scale groups x 64 lanes (R7 work distribution — measured
// best). Synchronization stripped to the bone:
//  - producer/consumer named barrier: warp-odd writes its 18 keys to smem
//    and bar.arrive's (non-blocking); only warp-even bar.sync's
//  - NO second barrier: each warp publishes its packed (cnt+1, sum) u64
//    directly to a global slot (st.cg, zero = pending sentinel)
//  - block 0 warp 0 polls all 6*B slots (3x v2.u64 loads/lane), combines
//    per scale in fixed order, writes the scalar, re-arms zeros.
//    No atomics, no fences anywhere.

#define NT   50
#define NA   3
#define NC   85
#define BMAX 32
#define THRESH 0.5f
#define FULL 0xffffffffu

__device__ unsigned long long g_pairs[BMAX * 6];   // zero-init = pending

__device__ __forceinline__ void st_cg64(unsigned long long* p, unsigned long long v) {
    asm volatile("st.global.cg.u64 [%0], %1;" :: "l"(p), "l"(v) : "memory");
}
__device__ __forceinline__ void ld_cg_v2(const unsigned long long* p,
                                         unsigned long long& a, unsigned long long& b) {
    asm volatile("ld.global.cg.v2.u64 {%0,%1}, [%2];"
                 : "=l"(a), "=l"(b) : "l"(p) : "memory");
}

__global__ void __launch_bounds__(192, 1)
box_loss_fused(const float* __restrict__ out0, const float* __restrict__ anc0,
               const float* __restrict__ out1, const float* __restrict__ anc1,
               const float* __restrict__ out2, const float* __restrict__ anc2,
               const float* __restrict__ targets,
               float* __restrict__ result, float invB)
{
    const int b    = blockIdx.x;
    const int B    = gridDim.x;
    const int tid  = threadIdx.x;
    const int g    = tid >> 6;          // scale group 0..2
    const int l    = tid & 63;          // lane in group (== target index)
    const int lane = tid & 31;
    const int wid  = tid >> 5;          // 0..5
    const bool odd = (l >= 32);

    __shared__ int skey18[3][18];       // warp-odd keys (targets 32..49)

    const float* out = (g == 0) ? out0 : (g == 1) ? out1 : out2;
    const float* anc = (g == 0) ? anc0 : (g == 1) ? anc1 : anc2;
    const int    G   = (g == 0) ? 52   : (g == 1) ? 26   : 13;
    const float  fG  = (float)G;

    // ---- all independent global loads issued immediately ----
    const float aw0 = __ldg(anc + 0), ah0 = __ldg(anc + 1);
    const float aw1 = __ldg(anc + 2), ah1 = __ldg(anc + 3);
    const float aw2 = __ldg(anc + 4), ah2 = __ldg(anc + 5);

    float x = 0.f, y = 0.f, w = 0.f, h = 0.f;
    if (l < NT) {
        const float* tg = targets + ((size_t)b * NT + l) * 5;
        x = __ldg(tg + 1); y = __ldg(tg + 2);
        w = __ldg(tg + 3); h = __ldg(tg + 4);
    }

    const bool  valid = (l < NT) && !(x == 0.f && y == 0.f && w == 0.f && h == 0.f);
    const float tx = x * fG, ty = y * fG, tw = w * fG, th = h * fG;
    const float cx = floorf(tx), cy = floorf(ty);
    const int   icx = (int)cx,   icy = (int)cy;
    const bool  inb = valid && icx >= 0 && icx < G && icy >= 0 && icy < G;

    // ---- IoU vs 3 anchors (areas from rect diffs, matching reference) ----
    const float zx = tx - cx - 0.5f, zy = ty - cy - 0.5f;
    const float t0 = zx - tw * 0.5f, t1 = zy - th * 0.5f;
    const float t2 = zx + tw * 0.5f, t3 = zy + th * 0.5f;
    const float area_t = (t2 - t0) * (t3 - t1);

    float overlap = -1.f;
    int   best = 0;
    #pragma unroll
    for (int a = 0; a < NA; a++) {
        const float w2 = ((a == 0) ? aw0 : (a == 1) ? aw1 : aw2) * 0.5f;
        const float h2 = ((a == 0) ? ah0 : (a == 1) ? ah1 : ah2) * 0.5f;
        const float x0 = fmaxf(t0, -w2), y0 = fmaxf(t1, -h2);
        const float x1 = fminf(t2,  w2), y1 = fminf(t3,  h2);
        const float inter  = (x0 < x1 && y0 < y1) ? (x1 - x0) * (y1 - y0) : 0.f;
        const float area_a = (2.f * w2) * (2.f * h2);
        const float iou = inter / (area_t + area_a - inter);
        if (iou > overlap) { overlap = iou; best = a; }   // first-max wins
    }

    const int key = (inb && overlap > THRESH) ? (best * G + icy) * G + icx : -1;

    // ---- producer side: odd warp exports keys then arrives (non-blocking) --
    if (odd) {
        if (l < NT) skey18[g][l - 32] = key;
        asm volatile("bar.arrive %0, 64;" :: "r"(g + 1) : "memory");
    }

    // ---- speculative gather (best anchor only) ----
    float px = 0.f, py = 0.f, pw = 1.f, ph = 1.f;
    if (key >= 0) {
        const float* c = out + ((long long)b * NA * G * G + key) * (long long)NC;
        px = __ldg(c + 0); py = __ldg(c + 1);
        pw = __ldg(c + 2); ph = __ldg(c + 3);
    }

    // ---- dup resolution: last target index wins ----
    const unsigned mmask = __match_any_sync(FULL, key);
    bool win = (key >= 0) && ((31 - __clz(mmask)) == lane);
    if (!odd) {
        asm volatile("bar.sync %0, 64;" :: "r"(g + 1) : "memory");
        if (win) {
            bool dup = false;
            #pragma unroll
            for (int j = 0; j < 18; j++)
                dup |= (skey18[g][j] == key);
            win = !dup;
        }
    }

    float sum = 0.f;
    if (win) {
        const float dx = px - tx, dy = py - ty;
        const float rw = rsqrtf(pw) - rsqrtf(tw);
        const float rh = rsqrtf(ph) - rsqrtf(th);
        sum = dx * dx + dy * dy + rw * rw + rh * rh;
    }
    const int cnt = __popc(__ballot_sync(FULL, win));

    // ---- warp reduce + per-warp publish (zero word = pending) ----
    #pragma unroll
    for (int off = 16; off > 0; off >>= 1)
        sum += __shfl_down_sync(FULL, sum, off);
    if (lane == 0) {
        const unsigned long long word =
            ((unsigned long long)(unsigned)(cnt + 1) << 32) |
            (unsigned long long)__float_as_uint(sum);
        st_cg64(&g_pairs[b * 6 + wid], word);
    }

    // ---- block 0, warp 0: poll 6 slots/lane, combine, write, re-arm ----
    if (b == 0 && tid < 32) {
        const bool mine = (tid < B);
        unsigned long long p0 = 1, p1 = 1, p2 = 1, p3 = 1, p4 = 1, p5 = 1;
        unsigned long long* slot = &g_pairs[tid * 6];
        for (;;) {
            if (mine) {
                ld_cg_v2(slot + 0, p0, p1);
                ld_cg_v2(slot + 2, p2, p3);
                ld_cg_v2(slot + 4, p4, p5);
            }
            const bool pending = mine &&
                ((p0 == 0ull) | (p1 == 0ull) | (p2 == 0ull) |
                 (p3 == 0ull) | (p4 == 0ull) | (p5 == 0ull));
            if (!__any_sync(FULL, pending)) break;
        }
        float s = 0.f;
        if (mine) {
            #pragma unroll
            for (int gg = 0; gg < 3; gg++) {
                const unsigned long long a = (gg == 0) ? p0 : (gg == 1) ? p2 : p4;
                const unsigned long long c = (gg == 0) ? p1 : (gg == 1) ? p3 : p5;
                const float t = __uint_as_float((unsigned)a) +
                                __uint_as_float((unsigned)c);
                const int   n = (int)(a >> 32) - 1 + (int)(c >> 32) - 1;
                if (n > 0) s += t / (2.0f * (float)n);
            }
        }
        #pragma unroll
        for (int off = 16; off > 0; off >>= 1)
            s += __shfl_down_sync(FULL, s, off);
        if (mine) {                      // re-arm sentinels for next replay
            st_cg64(slot + 0, 0ull); st_cg64(slot + 1, 0ull);
            st_cg64(slot + 2, 0ull); st_cg64(slot + 3, 0ull);
            st_cg64(slot + 4, 0ull); st_cg64(slot + 5, 0ull);
        }
        if (tid == 0) result[0] = s * invB;
    }
}

extern "C" void kernel_launch(void* const* d_in, const int* in_sizes, int n_in,
                              void* d_out, int out_size)
{
    const float* out0 = (const float*)d_in[0];
    const float* anc0 = (const float*)d_in[1];
    const float* out1 = (const float*)d_in[2];
    const float* anc1 = (const float*)d_in[3];
    const float* out2 = (const float*)d_in[4];
    const float* anc2 = (const float*)d_in[5];
    const float* tgts = (const float*)d_in[6];

    int B = in_sizes[6] / (NT * 5);
    if (B > BMAX) B = BMAX;

    box_loss_fused<<<B, 192>>>(out0, anc0, out1, anc1, out2, anc2, tgts,
                               (float*)d_out, 1.0f / (float)B);
}

// round 10
// speedup vs baseline: 1.0337x; 1.0337x over previous
#include <cuda_runtime.h>

// BoxLoss: 3-scale YOLO box loss. ONE launch, 32 blocks (1 image each),
// 192 threads = 3 scale groups x 64 lanes (R7 compute structure — measured
// best). Tail: each group does ONE counting atomicAdd carrying (tag, value)
// as packed fixed-point u64; the 96th arriver has the exact total in
// registers (old + own) -> writes the scalar directly. No polling, no
// fences, no extra loads. Integer accumulation = associative = exact
// deterministic result.

#define NT   50
#define NA   3
#define NC   85
#define BMAX 32
#define THRESH 0.5f
#define FULL 0xffffffffu
#define FIX  1073741824.0          // 2^30
#define TAG  (1ull << 52)
#define VALMASK ((1ull << 52) - 1ull)

__device__ unsigned long long g_acc = 0ull;

__device__ __forceinline__ void st_cg64(unsigned long long* p, unsigned long long v) {
    asm volatile("st.global.cg.u64 [%0], %1;" :: "l"(p), "l"(v) : "memory");
}
__device__ __forceinline__ void bar_group(int id) {
    asm volatile("bar.sync %0, 64;" :: "r"(id) : "memory");
}

__global__ void __launch_bounds__(192, 1)
box_loss_fused(const float* __restrict__ out0, const float* __restrict__ anc0,
               const float* __restrict__ out1, const float* __restrict__ anc1,
               const float* __restrict__ out2, const float* __restrict__ anc2,
               const float* __restrict__ targets,
               float* __restrict__ result, float invB)
{
    const int b    = blockIdx.x;
    const int B    = gridDim.x;
    const int tid  = threadIdx.x;
    const int g    = tid >> 6;          // scale group 0..2
    const int l    = tid & 63;          // lane in group (== target index)
    const int lane = tid & 31;
    const bool odd = (l >= 32);

    __shared__ int   skey18[3][18];     // warp-odd keys (targets 32..49)
    __shared__ float wsum[6];
    __shared__ int   wcnt[6];

    const float* out = (g == 0) ? out0 : (g == 1) ? out1 : out2;
    const float* anc = (g == 0) ? anc0 : (g == 1) ? anc1 : anc2;
    const int    G   = (g == 0) ? 52   : (g == 1) ? 26   : 13;
    const float  fG  = (float)G;

    // ---- all independent global loads issued immediately ----
    const float aw0 = __ldg(anc + 0), ah0 = __ldg(anc + 1);
    const float aw1 = __ldg(anc + 2), ah1 = __ldg(anc + 3);
    const float aw2 = __ldg(anc + 4), ah2 = __ldg(anc + 5);

    float x = 0.f, y = 0.f, w = 0.f, h = 0.f;
    if (l < NT) {
        const float* tg = targets + ((size_t)b * NT + l) * 5;
        x = __ldg(tg + 1); y = __ldg(tg + 2);
        w = __ldg(tg + 3); h = __ldg(tg + 4);
    }

    const bool  valid = (l < NT) && !(x == 0.f && y == 0.f && w == 0.f && h == 0.f);
    const float tx = x * fG, ty = y * fG, tw = w * fG, th = h * fG;
    const float cx = floorf(tx), cy = floorf(ty);
    const int   icx = (int)cx,   icy = (int)cy;
    const bool  inb = valid && icx >= 0 && icx < G && icy >= 0 && icy < G;

    // ---- IoU vs 3 anchors (areas from rect diffs, matching reference) ----
    const float zx = tx - cx - 0.5f, zy = ty - cy - 0.5f;
    const float t0 = zx - tw * 0.5f, t1 = zy - th * 0.5f;
    const float t2 = zx + tw * 0.5f, t3 = zy + th * 0.5f;
    const float area_t = (t2 - t0) * (t3 - t1);

    float overlap = -1.f;
    int   best = 0;
    #pragma unroll
    for (int a = 0; a < NA; a++) {
        const float w2 = ((a == 0) ? aw0 : (a == 1) ? aw1 : aw2) * 0.5f;
        const float h2 = ((a == 0) ? ah0 : (a == 1) ? ah1 : ah2) * 0.5f;
        const float x0 = fmaxf(t0, -w2), y0 = fmaxf(t1, -h2);
        const float x1 = fminf(t2,  w2), y1 = fminf(t3,  h2);
        const float inter  = (x0 < x1 && y0 < y1) ? (x1 - x0) * (y1 - y0) : 0.f;
        const float area_a = (2.f * w2) * (2.f * h2);
        const float iou = inter / (area_t + area_a - inter);
        if (iou > overlap) { overlap = iou; best = a; }   // first-max wins
    }

    const int key = (inb && overlap > THRESH) ? (best * G + icy) * G + icx : -1;
    if (odd && l < NT) skey18[g][l - 32] = key;

    // ---- speculative gather (best anchor only), overlaps barrier+dup ----
    float px = 0.f, py = 0.f, pw = 1.f, ph = 1.f;
    if (key >= 0) {
        const float* c = out + ((long long)b * NA * G * G + key) * (long long)NC;
        px = __ldg(c + 0); py = __ldg(c + 1);
        pw = __ldg(c + 2); ph = __ldg(c + 3);
    }
    bar_group(g + 1);          // skey18 visible within the group

    // ---- collision resolution: last target index wins ----
    const unsigned mmask = __match_any_sync(FULL, key);
    bool win = (key >= 0) && ((31 - __clz(mmask)) == lane);
    if (!odd && win) {
        bool dup = false;
        #pragma unroll
        for (int j = 0; j < 18; j++)
            dup |= (skey18[g][j] == key);
        win = !dup;
    }

    float sum = 0.f;
    if (win) {
        const float dx = px - tx, dy = py - ty;
        const float rw = rsqrtf(pw) - rsqrtf(tw);
        const float rh = rsqrtf(ph) - rsqrtf(th);
        sum = dx * dx + dy * dy + rw * rw + rh * rh;
    }
    const int cnt = __popc(__ballot_sync(FULL, win));

    // ---- warp reduce + intra-group combine ----
    #pragma unroll
    for (int off = 16; off > 0; off >>= 1)
        sum += __shfl_down_sync(FULL, sum, off);

    const int wid = tid >> 5;
    if (lane == 0) { wsum[wid] = sum; wcnt[wid] = cnt; }
    bar_group(g + 1);

    // ---- single counting atomic: tag + fixed-point value in one u64 ----
    if (l == 0) {
        const float t = wsum[2 * g] + wsum[2 * g + 1];
        const int   n = wcnt[2 * g] + wcnt[2 * g + 1];
        const float loss = (n > 0) ? t / (2.0f * (float)n) : 0.f;
        const unsigned long long pack =
            TAG | (unsigned long long)(long long)((double)loss * FIX);
        const unsigned long long old = atomicAdd(&g_acc, pack);
        if ((old >> 52) == (unsigned long long)(3 * B - 1)) {
            // this was the 96th arrival: total is in registers, no reload
            const unsigned long long total = old + pack;
            const double s = (double)(long long)(total & VALMASK) * (1.0 / FIX);
            result[0] = (float)s * invB;
            st_cg64(&g_acc, 0ull);       // re-arm for next graph replay
        }
    }
}

extern "C" void kernel_launch(void* const* d_in, const int* in_sizes, int n_in,
                              void* d_out, int out_size)
{
    const float* out0 = (const float*)d_in[0];
    const float* anc0 = (const float*)d_in[1];
    const float* out1 = (const float*)d_in[2];
    const float* anc1 = (const float*)d_in[3];
    const float* out2 = (const float*)d_in[4];
    const float* anc2 = (const float*)d_in[5];
    const float* tgts = (const float*)d_in[6];

    int B = in_sizes[6] / (NT * 5);
    if (B > BMAX) B = BMAX;

    box_loss_fused<<<B, 192>>>(out0, anc0, out1, anc1, out2, anc2, tgts,
                               (float*)d_out, 1.0f / (float)B);
}